// round 16
// baseline (speedup 1.0000x reference)
#include <cuda_runtime.h>
#include <cuda_fp16.h>
#include <math.h>

namespace {
constexpr int Bsz = 256;   // batch
constexpr int Tt  = 200;   // time steps
constexpr int Xd  = 128;   // input dim
constexpr int Hd  = 512;   // hidden
constexpr int NU  = 100;   // bottleneck
constexpr int CIN = 2 * Hd + Xd;   // 1152
constexpr int RPB = 2;             // batch rows per CTA
constexpr int NBLK = Bsz / RPB;    // 128 CTAs
constexpr int NTHR = 1024;

constexpr int SZ_W1 = CIN * NU;        // 115200 (Wu1, Wr1, Wn1)
constexpr int SZ_W2 = NU * Hd;         // 51200  (Wu2, Wr2, Wo1T-ish, Wo2)
constexpr int SZ_WN2 = NU * 2 * Hd;    // 102400 (Wn2)
constexpr int SZ_WO1 = Hd * NU;        // 51200
}

// fp16 weight scratch (conversion is captured in the graph, runs every replay)
__device__ __half g_Wu1h[SZ_W1];
__device__ __half g_Wr1h[SZ_W1];
__device__ __half g_Wn1h[SZ_W1];
__device__ __half g_Wu2h[SZ_W2];
__device__ __half g_Wr2h[SZ_W2];
__device__ __half g_Wn2h[SZ_WN2];
__device__ __half g_Wo1h[SZ_WO1];
__device__ __half g_Wo2h[SZ_W2];

__global__ void convert_weights(const float* __restrict__ Wu1,
                                const float* __restrict__ Wr1,
                                const float* __restrict__ Wn1,
                                const float* __restrict__ Wu2,
                                const float* __restrict__ Wr2,
                                const float* __restrict__ Wn2,
                                const float* __restrict__ Wo1,
                                const float* __restrict__ Wo2) {
    int i = blockIdx.x * blockDim.x + threadIdx.x;
    int stride = gridDim.x * blockDim.x;
    for (int k = i; k < SZ_W1; k += stride) {
        g_Wu1h[k] = __float2half(Wu1[k]);
        g_Wr1h[k] = __float2half(Wr1[k]);
        g_Wn1h[k] = __float2half(Wn1[k]);
    }
    for (int k = i; k < SZ_W2; k += stride) {
        g_Wu2h[k] = __float2half(Wu2[k]);
        g_Wr2h[k] = __float2half(Wr2[k]);
        g_Wo2h[k] = __float2half(Wo2[k]);
    }
    for (int k = i; k < SZ_WN2; k += stride) g_Wn2h[k] = __float2half(Wn2[k]);
    for (int k = i; k < SZ_WO1; k += stride) g_Wo1h[k] = __float2half(Wo1[k]);
}

struct SMem {
    float h[RPB][Hd];
    float hs[RPB][Hd];
    float hode[RPB][Hd];
    float ug[RPB][Hd];
    float cc[RPB][CIN];
    float t1[RPB][NU];
    float p1[RPB][NU];
    float p2[RPB][NU];
    float spart[4096];   // union: part(s,r,j)=[(s*2+r)*100+j] (16 groups) OR
                         //        part2(s,r,c)=[(s*2+r)*1024+c] (2 splits)
    float dt;
};

__device__ __forceinline__ float sigmoidf_(float x) {
    return 1.0f / (1.0f + expf(-x));
}

// fp16-weight dotpair: both batch rows, adjacent col pair (j0 even). K even.
// Wp = &W[K0*ldw + j0] (__half, 4B-aligned since ldw,j0 even).
template <int K>
__device__ __forceinline__ void dotpair_h(const float* __restrict__ in0,
                                          const float* __restrict__ in1,
                                          const __half* __restrict__ Wp, int ldw,
                                          float2& o0, float2& o1) {
    float a00=0.f,a01=0.f,a10=0.f,a11=0.f;
    float b00=0.f,b01=0.f,b10=0.f,b11=0.f;
#pragma unroll 4
    for (int k = 0; k < K; k += 2) {
        float2 w0 = __half22float2(__ldg((const __half2*)(Wp + (k    ) * ldw)));
        float2 w1 = __half22float2(__ldg((const __half2*)(Wp + (k + 1) * ldw)));
        float x00 = in0[k], x01 = in0[k + 1];
        float x10 = in1[k], x11 = in1[k + 1];
        a00 = fmaf(x00, w0.x, a00); a01 = fmaf(x00, w0.y, a01);
        a10 = fmaf(x10, w0.x, a10); a11 = fmaf(x10, w0.y, a11);
        b00 = fmaf(x01, w1.x, b00); b01 = fmaf(x01, w1.y, b01);
        b10 = fmaf(x11, w1.x, b10); b11 = fmaf(x11, w1.y, b11);
    }
    o0 = make_float2(a00 + b00, a01 + b01);
    o1 = make_float2(a10 + b10, a11 + b11);
}

// fp32 dotpair (head only)
template <int K>
__device__ __forceinline__ void dotpair(const float* __restrict__ in0,
                                        const float* __restrict__ in1,
                                        const float* __restrict__ Wp, int ldw,
                                        float2& o0, float2& o1) {
    float a00=0.f,a01=0.f,a10=0.f,a11=0.f;
    float b00=0.f,b01=0.f,b10=0.f,b11=0.f;
#pragma unroll 4
    for (int k = 0; k < K; k += 2) {
        float2 w0 = __ldg((const float2*)(Wp + (k    ) * ldw));
        float2 w1 = __ldg((const float2*)(Wp + (k + 1) * ldw));
        float x00 = in0[k], x01 = in0[k + 1];
        float x10 = in1[k], x11 = in1[k + 1];
        a00 = fmaf(x00, w0.x, a00); a01 = fmaf(x00, w0.y, a01);
        a10 = fmaf(x10, w0.x, a10); a11 = fmaf(x10, w0.y, a11);
        b00 = fmaf(x01, w1.x, b00); b01 = fmaf(x01, w1.y, b01);
        b10 = fmaf(x11, w1.x, b10); b11 = fmaf(x11, w1.y, b11);
    }
    o0 = make_float2(a00 + b00, a01 + b01);
    o1 = make_float2(a10 + b10, a11 + b11);
}

// scalar column dot, 4 chains (head only, K=100)
template <int K>
__device__ __forceinline__ float dot4(const float* __restrict__ in,
                                      const float* __restrict__ W,
                                      int ldw, int j) {
    float a0=0.f,a1=0.f,a2=0.f,a3=0.f;
    const float* Wp = W + j;
#pragma unroll 4
    for (int k = 0; k < K; k += 4) {
        a0 = fmaf(in[k+0], __ldg(&Wp[(k+0)*ldw]), a0);
        a1 = fmaf(in[k+1], __ldg(&Wp[(k+1)*ldw]), a1);
        a2 = fmaf(in[k+2], __ldg(&Wp[(k+2)*ldw]), a2);
        a3 = fmaf(in[k+3], __ldg(&Wp[(k+3)*ldw]), a3);
    }
    return (a0+a1)+(a2+a3);
}

__global__ void __launch_bounds__(NTHR, 1)
ode_gru_kernel(const float* __restrict__ x_data, const float* __restrict__ x_time,
               const float* __restrict__ bu1, const float* __restrict__ bu2,
               const float* __restrict__ br1, const float* __restrict__ br2,
               const float* __restrict__ bn1, const float* __restrict__ bn2,
               const float* __restrict__ bo1, const float* __restrict__ bo2,
               const float* __restrict__ Wt1, const float* __restrict__ bt1,
               const float* __restrict__ Wt2, const float* __restrict__ bt2,
               const float* __restrict__ Wt3, const float* __restrict__ bt3,
               float* __restrict__ out) {
    __shared__ SMem sm;
    const int t = threadIdx.x;
    const int row0 = blockIdx.x * RPB;

    const __half* Wu1h = g_Wu1h;
    const __half* Wr1h = g_Wr1h;
    const __half* Wn1h = g_Wn1h;
    const __half* Wu2h = g_Wu2h;
    const __half* Wr2h = g_Wr2h;
    const __half* Wn2h = g_Wn2h;
    const __half* Wo1h = g_Wo1h;
    const __half* Wo2h = g_Wo2h;

    // init state; cc hs-part must be 0 for step 0's P3
    for (int i = t; i < RPB * Hd; i += NTHR) {
        (&sm.h[0][0])[i] = 0.f;
        (&sm.hs[0][0])[i] = 0.f;
        int r = i / Hd, j = i % Hd;
        sm.cc[r][Hd + j] = 0.f;
    }
    __syncthreads();

    for (int step = 0; step < Tt; step++) {
        // x loader -> cc x-part; dt
        if (t < RPB * Xd) {
            int r = t / Xd, i = t % Xd;
            sm.cc[r][2 * Hd + i] =
                x_data[(long)(row0 + r) * Tt * Xd + (long)step * Xd + i];
        }
        if (t == 0) {
            float dtv;
            if (step == 0)      dtv = -0.01f;
            else if (step == 1) dtv = x_time[Tt - 1] - x_time[0];
            else                dtv = x_time[step - 2] - x_time[step - 1];
            sm.dt = dtv;
        }
        __syncthreads();

        // P1: partials of h @ Wo1  (K=512 -> 16 splits of 32; 50 col-pairs)
        if (t < 800) {
            int s = t / 50, jp = t % 50, j0 = 2 * jp;
            int K0 = s * 32;
            float2 o0, o1;
            dotpair_h<32>(sm.h[0] + K0, sm.h[1] + K0, Wo1h + K0 * NU + j0, NU, o0, o1);
            float* P = sm.spart + (s * 2) * NU + j0;
            P[0] = o0.x; P[1] = o0.y;            // row 0: group s*2
            P[NU] = o1.x; P[NU + 1] = o1.y;      // row 1: group s*2+1
        }
        __syncthreads();
        // P1c: t1 = tanh(sum + bo1)
        if (t < RPB * NU) {
            int r = t / NU, j = t % NU;
            float sum = __ldg(&bo1[j]);
#pragma unroll
            for (int s = 0; s < 16; s++) sum += sm.spart[(s * 2 + r) * NU + j];
            sm.t1[r][j] = tanhf(sum);
        }
        __syncthreads();

        // P2: partials of t1 @ Wo2  (K=100 -> 2 splits of 50; 256 col-pairs)
        if (t < 512) {
            int s = t / 256, jp = t % 256, j0 = 2 * jp;
            int K0 = s * 50;
            float2 o0, o1;
            dotpair_h<50>(sm.t1[0] + K0, sm.t1[1] + K0, Wo2h + K0 * Hd + j0, Hd, o0, o1);
            float* P = sm.spart + (s * 2) * 1024 + j0;
            P[0] = o0.x; P[1] = o0.y;
            P[1024] = o1.x; P[1024 + 1] = o1.y;
        }
        __syncthreads();
        // P2c: hode = h + dt*(sum + bo2); also cc h-part
        if (t < Hd) {
            int j = t;
            float bb = __ldg(&bo2[j]);
            float dtv = sm.dt;
#pragma unroll
            for (int r = 0; r < RPB; r++) {
                float v = sm.spart[r * 1024 + j] + sm.spart[(2 + r) * 1024 + j] + bb;
                float ho = sm.h[r][j] + dtv * v;
                sm.hode[r][j] = ho;
                sm.cc[r][j] = ho;
            }
        }
        __syncthreads();

        // P3: partials of cc @ {Wu1,Wr1}  (K=1152 -> 8 splits of 144; 2 gates)
        if (t < 800) {
            int g = t / 400, rem = t % 400;
            int s = rem / 50, jp = rem % 50, j0 = 2 * jp;
            int K0 = s * 144;
            const __half* W = g ? Wr1h : Wu1h;
            float2 o0, o1;
            dotpair_h<144>(sm.cc[0] + K0, sm.cc[1] + K0, W + K0 * NU + j0, NU, o0, o1);
            float* P = sm.spart + ((g * 8 + s) * 2) * NU + j0;
            P[0] = o0.x; P[1] = o0.y;
            P[NU] = o1.x; P[NU + 1] = o1.y;
        }
        __syncthreads();
        // P3c: p1/p2 = tanh(sum + b)
        if (t < 400) {
            int g = t / 200, rem = t % 200;
            int r = rem / NU, j = rem % NU;
            float sum = __ldg(&(g ? br1 : bu1)[j]);
#pragma unroll
            for (int s = 0; s < 8; s++)
                sum += sm.spart[((g * 8 + s) * 2 + r) * NU + j];
            float v = tanhf(sum);
            if (g) sm.p2[r][j] = v; else sm.p1[r][j] = v;
        }
        __syncthreads();

        // P4: partials of {p1@Wu2, p2@Wr2}  (K=100 -> 2 splits; 2 gates x 256 pairs)
        {
            int g = t / 512, rem = t % 512;
            int s = rem / 256, jp = rem % 256, j0 = 2 * jp;
            int K0 = s * 50;
            const __half* W2 = g ? Wr2h : Wu2h;
            const float* i0 = g ? sm.p2[0] : sm.p1[0];
            const float* i1 = g ? sm.p2[1] : sm.p1[1];
            float2 o0, o1;
            dotpair_h<50>(i0 + K0, i1 + K0, W2 + K0 * Hd + j0, Hd, o0, o1);
            float* P = sm.spart + (s * 2) * 1024 + g * Hd + j0;
            P[0] = o0.x; P[1] = o0.y;
            P[1024] = o1.x; P[1024 + 1] = o1.y;
        }
        __syncthreads();
        // P4c: u -> ug; r -> write r-scaled cc directly
        {
            int g = t / 512, j = t % 512;
            float bb = __ldg(&(g ? br2 : bu2)[j]);
            int c = g * Hd + j;
#pragma unroll
            for (int r = 0; r < RPB; r++) {
                float v = sm.spart[r * 1024 + c] + sm.spart[(2 + r) * 1024 + c] + bb;
                float gv = sigmoidf_(v);
                if (g == 0) {
                    sm.ug[r][j] = gv;
                } else {
                    sm.cc[r][j]      = sm.hode[r][j] * gv;
                    sm.cc[r][Hd + j] = sm.hs[r][j] * gv;
                }
            }
        }
        __syncthreads();

        // P5: partials of cc_r @ Wn1  (K=1152 -> 16 splits of 72)
        if (t < 800) {
            int s = t / 50, jp = t % 50, j0 = 2 * jp;
            int K0 = s * 72;
            float2 o0, o1;
            dotpair_h<72>(sm.cc[0] + K0, sm.cc[1] + K0, Wn1h + K0 * NU + j0, NU, o0, o1);
            float* P = sm.spart + (s * 2) * NU + j0;
            P[0] = o0.x; P[1] = o0.y;
            P[NU] = o1.x; P[NU + 1] = o1.y;
        }
        __syncthreads();
        // P5c
        if (t < RPB * NU) {
            int r = t / NU, j = t % NU;
            float sum = __ldg(&bn1[j]);
#pragma unroll
            for (int s = 0; s < 16; s++) sum += sm.spart[(s * 2 + r) * NU + j];
            sm.p1[r][j] = tanhf(sum);
        }
        __syncthreads();

        // P6: partials of p1 @ Wn2  (N=1024, K=100 -> 2 splits; 512 pairs)
        {
            int s = t / 512, jp = t % 512, j0 = 2 * jp;
            int K0 = s * 50;
            float2 o0, o1;
            dotpair_h<50>(sm.p1[0] + K0, sm.p1[1] + K0, Wn2h + K0 * 2 * Hd + j0,
                          2 * Hd, o0, o1);
            float* P = sm.spart + (s * 2) * 1024 + j0;
            P[0] = o0.x; P[1] = o0.y;
            P[1024] = o1.x; P[1024 + 1] = o1.y;
        }
        __syncthreads();
        // P6c: state update; also next-step cc hs-part
        {
            int c = t;
            float bb = __ldg(&bn2[c]);
#pragma unroll
            for (int r = 0; r < RPB; r++) {
                float v = sm.spart[r * 1024 + c] + sm.spart[(2 + r) * 1024 + c] + bb;
                if (c < Hd) {
                    int j = c;
                    float u = sm.ug[r][j];
                    sm.h[r][j] = (1.f - u) * v + u * sm.hode[r][j];
                } else {
                    int j = c - Hd;
                    float u = sm.ug[r][j];
                    float ns = (1.f - u) * fabsf(v) + u * sm.hs[r][j];
                    sm.hs[r][j] = ns;
                    sm.cc[r][Hd + j] = ns;   // hs-part of cc for next step
                }
            }
        }
        __syncthreads();
    }

    // ---- Output head (runs once; fp32 weights for accuracy) ----
    // cc = [hT, hsT]
    for (int i = t; i < RPB * 2 * Hd; i += NTHR) {
        int r = i / (2 * Hd), k = i % (2 * Hd);
        sm.cc[r][k] = (k < Hd) ? sm.h[r][k] : sm.hs[r][k - Hd];
    }
    __syncthreads();

    // z1 = tanh(hcat @ Wt1 + bt1)  (K=1024 -> 16 splits of 64)
    if (t < 800) {
        int s = t / 50, jp = t % 50, j0 = 2 * jp;
        int K0 = s * 64;
        float2 o0, o1;
        dotpair<64>(sm.cc[0] + K0, sm.cc[1] + K0, Wt1 + K0 * NU + j0, NU, o0, o1);
        float* P = sm.spart + (s * 2) * NU + j0;
        P[0] = o0.x; P[1] = o0.y;
        P[NU] = o1.x; P[NU + 1] = o1.y;
    }
    __syncthreads();
    if (t < RPB * NU) {
        int r = t / NU, j = t % NU;
        float sum = __ldg(&bt1[j]);
#pragma unroll
        for (int s = 0; s < 16; s++) sum += sm.spart[(s * 2 + r) * NU + j];
        sm.t1[r][j] = tanhf(sum);
    }
    __syncthreads();

    // z2 = tanh(z1 @ Wt2 + bt2)  (K=100, N=100)
    if (t < RPB * NU) {
        int r = t / NU, j = t % NU;
        sm.p1[r][j] = tanhf(dot4<NU>(sm.t1[r], Wt2, NU, j) + __ldg(&bt2[j]));
    }
    __syncthreads();

    // z3 = z2 @ Wt3 + bt3  (N=1024, K=100 -> 2 splits)
    {
        int s = t / 512, jp = t % 512, j0 = 2 * jp;
        int K0 = s * 50;
        float2 o0, o1;
        dotpair<50>(sm.p1[0] + K0, sm.p1[1] + K0, Wt3 + K0 * 2 * Hd + j0,
                    2 * Hd, o0, o1);
        float* P = sm.spart + (s * 2) * 1024 + j0;
        P[0] = o0.x; P[1] = o0.y;
        P[1024] = o1.x; P[1024 + 1] = o1.y;
    }
    __syncthreads();
    {
        int c = t;
        float bb = __ldg(&bt3[c]);
#pragma unroll
        for (int r = 0; r < RPB; r++) {
            float v = sm.spart[r * 1024 + c] + sm.spart[(2 + r) * 1024 + c] + bb;
            if (c < Hd) {
                out[(long)(row0 + r) * Hd + c] = v;
            } else {
                long base = (long)Bsz * Hd;
                out[base + (long)(row0 + r) * Hd + (c - Hd)] = fabsf(v);
            }
        }
    }
}

extern "C" void kernel_launch(void* const* d_in, const int* in_sizes, int n_in,
                              void* d_out, int out_size) {
    const float* x_data = (const float*)d_in[0];
    const float* x_time = (const float*)d_in[1];
    const float* Wu1 = (const float*)d_in[2];
    const float* bu1 = (const float*)d_in[3];
    const float* Wu2 = (const float*)d_in[4];
    const float* bu2 = (const float*)d_in[5];
    const float* Wr1 = (const float*)d_in[6];
    const float* br1 = (const float*)d_in[7];
    const float* Wr2 = (const float*)d_in[8];
    const float* br2 = (const float*)d_in[9];
    const float* Wn1 = (const float*)d_in[10];
    const float* bn1 = (const float*)d_in[11];
    const float* Wn2 = (const float*)d_in[12];
    const float* bn2 = (const float*)d_in[13];
    const float* Wo1 = (const float*)d_in[14];
    const float* bo1 = (const float*)d_in[15];
    const float* Wo2 = (const float*)d_in[16];
    const float* bo2 = (const float*)d_in[17];
    const float* Wt1 = (const float*)d_in[18];
    const float* bt1 = (const float*)d_in[19];
    const float* Wt2 = (const float*)d_in[20];
    const float* bt2 = (const float*)d_in[21];
    const float* Wt3 = (const float*)d_in[22];
    const float* bt3 = (const float*)d_in[23];

    convert_weights<<<640, 256>>>(Wu1, Wr1, Wn1, Wu2, Wr2, Wn2, Wo1, Wo2);

    ode_gru_kernel<<<NBLK, NTHR>>>(x_data, x_time,
                                   bu1, bu2, br1, br2, bn1, bn2, bo1, bo2,
                                   Wt1, bt1, Wt2, bt2, Wt3, bt3,
                                   (float*)d_out);
}

// round 17
// speedup vs baseline: 1.0695x; 1.0695x over previous
#include <cuda_runtime.h>
#include <math.h>

namespace {
constexpr int Bsz = 256;   // batch
constexpr int Tt  = 200;   // time steps
constexpr int Xd  = 128;   // input dim
constexpr int Hd  = 512;   // hidden
constexpr int NU  = 100;   // bottleneck
constexpr int CIN = 2 * Hd + Xd;   // 1152
constexpr int RPB = 2;             // batch rows per CTA
constexpr int NBLK = Bsz / RPB;    // 128 CTAs
constexpr int NTHR = 1024;
}

struct SMem {
    float h[RPB][Hd];
    float hs[RPB][Hd];
    float hode[RPB][Hd];
    float ug[RPB][Hd];
    float cc[RPB][CIN];
    float t1[RPB][NU];
    float p1[RPB][NU];
    float p2[RPB][NU];
    float spart[6400];   // union: part(g,r,j)=[(g*2+r)*100+j] (up to 32 groups)
                         //        part2(s,r,c)=[(s*2+r)*1024+c] (2 splits)
    float dt;
};

__device__ __forceinline__ float sigmoidf_(float x) {
    return 1.0f / (1.0f + expf(-x));
}

// Quad-column dot: both batch rows, 4 adjacent cols (j0 % 4 == 0). K even.
// Wp = &W[K0*ldw + j0], 16B-aligned (ldw % 4 == 0, j0 % 4 == 0).
template <int K>
__device__ __forceinline__ void dotquad(const float* __restrict__ in0,
                                        const float* __restrict__ in1,
                                        const float* __restrict__ Wp, int ldw,
                                        float4& o0, float4& o1) {
    float a00=0.f,a01=0.f,a02=0.f,a03=0.f;   // row0, even k
    float a10=0.f,a11=0.f,a12=0.f,a13=0.f;   // row1, even k
    float b00=0.f,b01=0.f,b02=0.f,b03=0.f;   // row0, odd k
    float b10=0.f,b11=0.f,b12=0.f,b13=0.f;   // row1, odd k
#pragma unroll 2
    for (int k = 0; k < K; k += 2) {
        float4 w0 = __ldg((const float4*)(Wp + (k    ) * ldw));
        float4 w1 = __ldg((const float4*)(Wp + (k + 1) * ldw));
        float x00 = in0[k], x01 = in0[k + 1];
        float x10 = in1[k], x11 = in1[k + 1];
        a00 = fmaf(x00, w0.x, a00); a01 = fmaf(x00, w0.y, a01);
        a02 = fmaf(x00, w0.z, a02); a03 = fmaf(x00, w0.w, a03);
        a10 = fmaf(x10, w0.x, a10); a11 = fmaf(x10, w0.y, a11);
        a12 = fmaf(x10, w0.z, a12); a13 = fmaf(x10, w0.w, a13);
        b00 = fmaf(x01, w1.x, b00); b01 = fmaf(x01, w1.y, b01);
        b02 = fmaf(x01, w1.z, b02); b03 = fmaf(x01, w1.w, b03);
        b10 = fmaf(x11, w1.x, b10); b11 = fmaf(x11, w1.y, b11);
        b12 = fmaf(x11, w1.z, b12); b13 = fmaf(x11, w1.w, b13);
    }
    o0 = make_float4(a00 + b00, a01 + b01, a02 + b02, a03 + b03);
    o1 = make_float4(a10 + b10, a11 + b11, a12 + b12, a13 + b13);
}

// Pair-column dot (wide-N phases P2/P4/P6 + head)
template <int K>
__device__ __forceinline__ void dotpair(const float* __restrict__ in0,
                                        const float* __restrict__ in1,
                                        const float* __restrict__ Wp, int ldw,
                                        float2& o0, float2& o1) {
    float a00=0.f,a01=0.f,a10=0.f,a11=0.f;
    float b00=0.f,b01=0.f,b10=0.f,b11=0.f;
#pragma unroll 4
    for (int k = 0; k < K; k += 2) {
        float2 w0 = __ldg((const float2*)(Wp + (k    ) * ldw));
        float2 w1 = __ldg((const float2*)(Wp + (k + 1) * ldw));
        float x00 = in0[k], x01 = in0[k + 1];
        float x10 = in1[k], x11 = in1[k + 1];
        a00 = fmaf(x00, w0.x, a00); a01 = fmaf(x00, w0.y, a01);
        a10 = fmaf(x10, w0.x, a10); a11 = fmaf(x10, w0.y, a11);
        b00 = fmaf(x01, w1.x, b00); b01 = fmaf(x01, w1.y, b01);
        b10 = fmaf(x11, w1.x, b10); b11 = fmaf(x11, w1.y, b11);
    }
    o0 = make_float2(a00 + b00, a01 + b01);
    o1 = make_float2(a10 + b10, a11 + b11);
}

// scalar column dot, 4 chains (head only, K=100)
template <int K>
__device__ __forceinline__ float dot4(const float* __restrict__ in,
                                      const float* __restrict__ W,
                                      int ldw, int j) {
    float a0=0.f,a1=0.f,a2=0.f,a3=0.f;
    const float* Wp = W + j;
#pragma unroll 4
    for (int k = 0; k < K; k += 4) {
        a0 = fmaf(in[k+0], __ldg(&Wp[(k+0)*ldw]), a0);
        a1 = fmaf(in[k+1], __ldg(&Wp[(k+1)*ldw]), a1);
        a2 = fmaf(in[k+2], __ldg(&Wp[(k+2)*ldw]), a2);
        a3 = fmaf(in[k+3], __ldg(&Wp[(k+3)*ldw]), a3);
    }
    return (a0+a1)+(a2+a3);
}

__global__ void __launch_bounds__(NTHR, 1)
ode_gru_kernel(const float* __restrict__ x_data, const float* __restrict__ x_time,
               const float* __restrict__ Wu1, const float* __restrict__ bu1,
               const float* __restrict__ Wu2, const float* __restrict__ bu2,
               const float* __restrict__ Wr1, const float* __restrict__ br1,
               const float* __restrict__ Wr2, const float* __restrict__ br2,
               const float* __restrict__ Wn1, const float* __restrict__ bn1,
               const float* __restrict__ Wn2, const float* __restrict__ bn2,
               const float* __restrict__ Wo1, const float* __restrict__ bo1,
               const float* __restrict__ Wo2, const float* __restrict__ bo2,
               const float* __restrict__ Wt1, const float* __restrict__ bt1,
               const float* __restrict__ Wt2, const float* __restrict__ bt2,
               const float* __restrict__ Wt3, const float* __restrict__ bt3,
               float* __restrict__ out) {
    __shared__ SMem sm;
    const int t = threadIdx.x;
    const int row0 = blockIdx.x * RPB;

    // init state; cc hs-part must be 0 for step 0's P3
    for (int i = t; i < RPB * Hd; i += NTHR) {
        (&sm.h[0][0])[i] = 0.f;
        (&sm.hs[0][0])[i] = 0.f;
        int r = i / Hd, j = i % Hd;
        sm.cc[r][Hd + j] = 0.f;
    }
    __syncthreads();

    for (int step = 0; step < Tt; step++) {
        // P1: partials of h @ Wo1  (K=512 -> 32 splits of 16; 25 col-quads)
        // Concurrent: warps 25-31 load x -> cc x-part and dt (ordered by P1's
        // barrier before first consumer P3/P2c; previous-step readers of cc
        // x-part finished before the P6c barrier that precedes loop entry).
        if (t < 800) {
            int s = t / 25, jp = t % 25, j0 = 4 * jp;
            int K0 = s * 16;
            float4 o0, o1;
            dotquad<16>(sm.h[0] + K0, sm.h[1] + K0, Wo1 + K0 * NU + j0, NU, o0, o1);
            float* P = sm.spart + (s * 2) * NU + j0;
            *(float4*)(P)      = o0;   // row 0: group s*2
            *(float4*)(P + NU) = o1;   // row 1: group s*2+1
        } else {
            for (int q = t - 800; q < RPB * Xd; q += 224) {
                int r = q >> 7, ii = q & (Xd - 1);
                sm.cc[r][2 * Hd + ii] =
                    x_data[(long)(row0 + r) * Tt * Xd + (long)step * Xd + ii];
            }
            if (t == 1023) {
                float dtv;
                if (step == 0)      dtv = -0.01f;
                else if (step == 1) dtv = x_time[Tt - 1] - x_time[0];
                else                dtv = x_time[step - 2] - x_time[step - 1];
                sm.dt = dtv;
            }
        }
        __syncthreads();
        // P1c: t1 = tanh(sum + bo1)
        if (t < RPB * NU) {
            int r = t / NU, j = t % NU;
            float sum = __ldg(&bo1[j]);
#pragma unroll
            for (int s = 0; s < 32; s++) sum += sm.spart[(s * 2 + r) * NU + j];
            sm.t1[r][j] = tanhf(sum);
        }
        __syncthreads();

        // P2: partials of t1 @ Wo2  (K=100 -> 2 splits of 50; 256 col-pairs)
        if (t < 512) {
            int s = t / 256, jp = t % 256, j0 = 2 * jp;
            int K0 = s * 50;
            float2 o0, o1;
            dotpair<50>(sm.t1[0] + K0, sm.t1[1] + K0, Wo2 + K0 * Hd + j0, Hd, o0, o1);
            float* P = sm.spart + (s * 2) * 1024 + j0;
            P[0] = o0.x; P[1] = o0.y;
            P[1024] = o1.x; P[1024 + 1] = o1.y;
        }
        __syncthreads();
        // P2c: hode = h + dt*(sum + bo2); also cc h-part
        if (t < Hd) {
            int j = t;
            float bb = __ldg(&bo2[j]);
            float dtv = sm.dt;
#pragma unroll
            for (int r = 0; r < RPB; r++) {
                float v = sm.spart[r * 1024 + j] + sm.spart[(2 + r) * 1024 + j] + bb;
                float ho = sm.h[r][j] + dtv * v;
                sm.hode[r][j] = ho;
                sm.cc[r][j] = ho;
            }
        }
        __syncthreads();

        // P3: partials of cc @ {Wu1,Wr1}  (K=1152 -> 16 splits of 72; 2 gates)
        if (t < 800) {
            int g = t / 400, rem = t % 400;
            int s = rem / 25, jp = rem % 25, j0 = 4 * jp;
            int K0 = s * 72;
            const float* W = g ? Wr1 : Wu1;
            float4 o0, o1;
            dotquad<72>(sm.cc[0] + K0, sm.cc[1] + K0, W + K0 * NU + j0, NU, o0, o1);
            float* P = sm.spart + ((g * 16 + s) * 2) * NU + j0;
            *(float4*)(P)      = o0;
            *(float4*)(P + NU) = o1;
        }
        __syncthreads();
        // P3c: p1/p2 = tanh(sum + b)
        if (t < 400) {
            int g = t / 200, rem = t % 200;
            int r = rem / NU, j = rem % NU;
            float sum = __ldg(&(g ? br1 : bu1)[j]);
#pragma unroll
            for (int s = 0; s < 16; s++)
                sum += sm.spart[((g * 16 + s) * 2 + r) * NU + j];
            float v = tanhf(sum);
            if (g) sm.p2[r][j] = v; else sm.p1[r][j] = v;
        }
        __syncthreads();

        // P4: partials of {p1@Wu2, p2@Wr2}  (K=100 -> 2 splits; 2 gates x 256 pairs)
        {
            int g = t / 512, rem = t % 512;
            int s = rem / 256, jp = rem % 256, j0 = 2 * jp;
            int K0 = s * 50;
            const float* W2 = g ? Wr2 : Wu2;
            const float* i0 = g ? sm.p2[0] : sm.p1[0];
            const float* i1 = g ? sm.p2[1] : sm.p1[1];
            float2 o0, o1;
            dotpair<50>(i0 + K0, i1 + K0, W2 + K0 * Hd + j0, Hd, o0, o1);
            float* P = sm.spart + (s * 2) * 1024 + g * Hd + j0;
            P[0] = o0.x; P[1] = o0.y;
            P[1024] = o1.x; P[1024 + 1] = o1.y;
        }
        __syncthreads();
        // P4c: u -> ug; r -> write r-scaled cc directly
        {
            int g = t / 512, j = t % 512;
            float bb = __ldg(&(g ? br2 : bu2)[j]);
            int c = g * Hd + j;
#pragma unroll
            for (int r = 0; r < RPB; r++) {
                float v = sm.spart[r * 1024 + c] + sm.spart[(2 + r) * 1024 + c] + bb;
                float gv = sigmoidf_(v);
                if (g == 0) {
                    sm.ug[r][j] = gv;
                } else {
                    sm.cc[r][j]      = sm.hode[r][j] * gv;
                    sm.cc[r][Hd + j] = sm.hs[r][j] * gv;
                }
            }
        }
        __syncthreads();

        // P5: partials of cc_r @ Wn1  (K=1152 -> 32 splits of 36; 25 quads)
        if (t < 800) {
            int s = t / 25, jp = t % 25, j0 = 4 * jp;
            int K0 = s * 36;
            float4 o0, o1;
            dotquad<36>(sm.cc[0] + K0, sm.cc[1] + K0, Wn1 + K0 * NU + j0, NU, o0, o1);
            float* P = sm.spart + (s * 2) * NU + j0;
            *(float4*)(P)      = o0;
            *(float4*)(P + NU) = o1;
        }
        __syncthreads();
        // P5c
        if (t < RPB * NU) {
            int r = t / NU, j = t % NU;
            float sum = __ldg(&bn1[j]);
#pragma unroll
            for (int s = 0; s < 32; s++) sum += sm.spart[(s * 2 + r) * NU + j];
            sm.p1[r][j] = tanhf(sum);
        }
        __syncthreads();

        // P6: partials of p1 @ Wn2  (N=1024, K=100 -> 2 splits; 512 pairs)
        {
            int s = t / 512, jp = t % 512, j0 = 2 * jp;
            int K0 = s * 50;
            float2 o0, o1;
            dotpair<50>(sm.p1[0] + K0, sm.p1[1] + K0, Wn2 + K0 * 2 * Hd + j0,
                        2 * Hd, o0, o1);
            float* P = sm.spart + (s * 2) * 1024 + j0;
            P[0] = o0.x; P[1] = o0.y;
            P[1024] = o1.x; P[1024 + 1] = o1.y;
        }
        __syncthreads();
        // P6c: state update; also next-step cc hs-part
        {
            int c = t;
            float bb = __ldg(&bn2[c]);
#pragma unroll
            for (int r = 0; r < RPB; r++) {
                float v = sm.spart[r * 1024 + c] + sm.spart[(2 + r) * 1024 + c] + bb;
                if (c < Hd) {
                    int j = c;
                    float u = sm.ug[r][j];
                    sm.h[r][j] = (1.f - u) * v + u * sm.hode[r][j];
                } else {
                    int j = c - Hd;
                    float u = sm.ug[r][j];
                    float ns = (1.f - u) * fabsf(v) + u * sm.hs[r][j];
                    sm.hs[r][j] = ns;
                    sm.cc[r][Hd + j] = ns;   // hs-part of cc for next step
                }
            }
        }
        __syncthreads();
    }

    // ---- Output head (runs once) ----
    // cc = [hT, hsT]
    for (int i = t; i < RPB * 2 * Hd; i += NTHR) {
        int r = i / (2 * Hd), k = i % (2 * Hd);
        sm.cc[r][k] = (k < Hd) ? sm.h[r][k] : sm.hs[r][k - Hd];
    }
    __syncthreads();

    // z1 = tanh(hcat @ Wt1 + bt1)  (K=1024 -> 32 splits of 32; 25 quads)
    if (t < 800) {
        int s = t / 25, jp = t % 25, j0 = 4 * jp;
        int K0 = s * 32;
        float4 o0, o1;
        dotquad<32>(sm.cc[0] + K0, sm.cc[1] + K0, Wt1 + K0 * NU + j0, NU, o0, o1);
        float* P = sm.spart + (s * 2) * NU + j0;
        *(float4*)(P)      = o0;
        *(float4*)(P + NU) = o1;
    }
    __syncthreads();
    if (t < RPB * NU) {
        int r = t / NU, j = t % NU;
        float sum = __ldg(&bt1[j]);
#pragma unroll
        for (int s = 0; s < 32; s++) sum += sm.spart[(s * 2 + r) * NU + j];
        sm.t1[r][j] = tanhf(sum);
    }
    __syncthreads();

    // z2 = tanh(z1 @ Wt2 + bt2)  (K=100, N=100)
    if (t < RPB * NU) {
        int r = t / NU, j = t % NU;
        sm.p1[r][j] = tanhf(dot4<NU>(sm.t1[r], Wt2, NU, j) + __ldg(&bt2[j]));
    }
    __syncthreads();

    // z3 = z2 @ Wt3 + bt3  (N=1024, K=100 -> 2 splits)
    {
        int s = t / 512, jp = t % 512, j0 = 2 * jp;
        int K0 = s * 50;
        float2 o0, o1;
        dotpair<50>(sm.p1[0] + K0, sm.p1[1] + K0, Wt3 + K0 * 2 * Hd + j0,
                    2 * Hd, o0, o1);
        float* P = sm.spart + (s * 2) * 1024 + j0;
        P[0] = o0.x; P[1] = o0.y;
        P[1024] = o1.x; P[1024 + 1] = o1.y;
    }
    __syncthreads();
    {
        int c = t;
        float bb = __ldg(&bt3[c]);
#pragma unroll
        for (int r = 0; r < RPB; r++) {
            float v = sm.spart[r * 1024 + c] + sm.spart[(2 + r) * 1024 + c] + bb;
            if (c < Hd) {
                out[(long)(row0 + r) * Hd + c] = v;
            } else {
                long base = (long)Bsz * Hd;
                out[base + (long)(row0 + r) * Hd + (c - Hd)] = fabsf(v);
            }
        }
    }
}

extern "C" void kernel_launch(void* const* d_in, const int* in_sizes, int n_in,
                              void* d_out, int out_size) {
    const float* x_data = (const float*)d_in[0];
    const float* x_time = (const float*)d_in[1];
    const float* Wu1 = (const float*)d_in[2];
    const float* bu1 = (const float*)d_in[3];
    const float* Wu2 = (const float*)d_in[4];
    const float* bu2 = (const float*)d_in[5];
    const float* Wr1 = (const float*)d_in[6];
    const float* br1 = (const float*)d_in[7];
    const float* Wr2 = (const float*)d_in[8];
    const float* br2 = (const float*)d_in[9];
    const float* Wn1 = (const float*)d_in[10];
    const float* bn1 = (const float*)d_in[11];
    const float* Wn2 = (const float*)d_in[12];
    const float* bn2 = (const float*)d_in[13];
    const float* Wo1 = (const float*)d_in[14];
    const float* bo1 = (const float*)d_in[15];
    const float* Wo2 = (const float*)d_in[16];
    const float* bo2 = (const float*)d_in[17];
    const float* Wt1 = (const float*)d_in[18];
    const float* bt1 = (const float*)d_in[19];
    const float* Wt2 = (const float*)d_in[20];
    const float* bt2 = (const float*)d_in[21];
    const float* Wt3 = (const float*)d_in[22];
    const float* bt3 = (const float*)d_in[23];

    ode_gru_kernel<<<NBLK, NTHR>>>(x_data, x_time,
                                   Wu1, bu1, Wu2, bu2,
                                   Wr1, br1, Wr2, br2,
                                   Wn1, bn1, Wn2, bn2,
                                   Wo1, bo1, Wo2, bo2,
                                   Wt1, bt1, Wt2, bt2, Wt3, bt3,
                                   (float*)d_out);
}